// round 2
// baseline (speedup 1.0000x reference)
#include <cuda_runtime.h>
#include <math.h>

#define N_NODES 3072
#define FEAT    256
#define HEADS   8
#define DH      128
#define DOUT    64
#define MAXD    512   // max degree; binomial(3072,0.05) max ~200, 512 is safe

// ---------------- device scratch (static globals; no allocation) ----------------
__device__ float g_h[N_NODES * FEAT];            // merged input features
__device__ int   g_cols[N_NODES * MAXD];         // ELL adjacency
__device__ int   g_deg[N_NODES];
__device__ float g_Wh0[HEADS * N_NODES * DH];    // layer0 Wh per head
__device__ float g_act0[HEADS * N_NODES * DH];   // layer0 output (per-head contiguous)
__device__ float g_Wh1[HEADS * N_NODES * DH];    // layer1 Wh per head
__device__ float g_hc[N_NODES * HEADS * DH];     // layer1 output, head-concat layout
__device__ float g_Whc[N_NODES * DOUT];          // output-layer Wh
__device__ float g_f1[HEADS * N_NODES];
__device__ float g_f2[HEADS * N_NODES];

// ---------------- mergeState: h = x + (obs==1) * theta ----------------
__global__ void merge_state(const float* __restrict__ x, const int* __restrict__ obs,
                            const float* __restrict__ theta, float* __restrict__ h)
{
    int idx = blockIdx.x * blockDim.x + threadIdx.x;   // float4 units
    const int total = N_NODES * FEAT / 4;
    if (idx >= total) return;
    int row = idx / (FEAT / 4);
    float4 v = reinterpret_cast<const float4*>(x)[idx];
    if (obs[row] == 1) {
        float4 t = reinterpret_cast<const float4*>(theta)[idx % (FEAT / 4)];
        v.x += t.x; v.y += t.y; v.z += t.z; v.w += t.w;
    }
    reinterpret_cast<float4*>(h)[idx] = v;
}

// ---------------- build ELL adjacency (order within row irrelevant) ----------------
__global__ void build_ell(const float* __restrict__ adj, int* __restrict__ cols,
                          int* __restrict__ degs)
{
    int i = blockIdx.x;
    __shared__ int cnt;
    if (threadIdx.x == 0) cnt = 0;
    __syncthreads();
    const float* row = adj + (size_t)i * N_NODES;
    for (int j = threadIdx.x; j < N_NODES; j += blockDim.x) {
        if (row[j] > 0.f) {
            int p = atomicAdd(&cnt, 1);
            if (p < MAXD) cols[i * MAXD + p] = j;
        }
    }
    __syncthreads();
    if (threadIdx.x == 0) degs[i] = cnt < MAXD ? cnt : MAXD;
}

// ---------------- classic tiled fp32 batched GEMM: C = A @ B ----------------
template <int BM, int BN, int BK, int TM, int TN>
__global__ __launch_bounds__(256)
void sgemm_bat(const float* __restrict__ A, const float* __restrict__ B,
               float* __restrict__ C, int M, int Nn, int K,
               long sA, long sB, long sC)
{
    constexpr int TX = BN / TN;
    constexpr int TY = BM / TM;
    constexpr int NT = TX * TY;                  // 256
    __shared__ float As[BK][BM];
    __shared__ float Bs[BK][BN];

    int z = blockIdx.z;
    A += (long)z * sA;  B += (long)z * sB;  C += (long)z * sC;
    int bm = blockIdx.x, bn = blockIdx.y;
    int tid = threadIdx.x;
    int tx = tid % TX, ty = tid / TX;

    float acc[TM][TN];
    #pragma unroll
    for (int m = 0; m < TM; m++)
        #pragma unroll
        for (int n = 0; n < TN; n++) acc[m][n] = 0.f;

    constexpr int A_UNITS = BM * BK / 4;
    constexpr int B_UNITS = BK * BN / 4;

    for (int k0 = 0; k0 < K; k0 += BK) {
        for (int u = tid; u < A_UNITS; u += NT) {
            int r  = u / (BK / 4);
            int c4 = (u % (BK / 4)) * 4;
            float4 v = *reinterpret_cast<const float4*>(
                A + (long)(bm * BM + r) * K + k0 + c4);
            As[c4 + 0][r] = v.x; As[c4 + 1][r] = v.y;
            As[c4 + 2][r] = v.z; As[c4 + 3][r] = v.w;
        }
        for (int u = tid; u < B_UNITS; u += NT) {
            int r  = u / (BN / 4);
            int c4 = (u % (BN / 4)) * 4;
            *reinterpret_cast<float4*>(&Bs[r][c4]) =
                *reinterpret_cast<const float4*>(B + (long)(k0 + r) * Nn + bn * BN + c4);
        }
        __syncthreads();
        #pragma unroll
        for (int kk = 0; kk < BK; kk++) {
            float ra[TM], rb[TN];
            #pragma unroll
            for (int m = 0; m < TM; m++) ra[m] = As[kk][ty * TM + m];
            #pragma unroll
            for (int n = 0; n < TN; n++) rb[n] = Bs[kk][tx * TN + n];
            #pragma unroll
            for (int m = 0; m < TM; m++)
                #pragma unroll
                for (int n = 0; n < TN; n++) acc[m][n] += ra[m] * rb[n];
        }
        __syncthreads();
    }
    #pragma unroll
    for (int m = 0; m < TM; m++) {
        float* crow = C + (long)(bm * BM + ty * TM + m) * Nn + bn * BN + tx * TN;
        #pragma unroll
        for (int n = 0; n < TN; n++) crow[n] = acc[m][n];
    }
}

// ---------------- f1 = Wh . a[:D], f2 = Wh . a[D:] (one warp per row) ----------------
template <int D>
__global__ void calc_f12(const float* __restrict__ Wh, const float* __restrict__ a,
                         float* __restrict__ f1, float* __restrict__ f2, int total)
{
    int warp = (blockIdx.x * blockDim.x + threadIdx.x) >> 5;
    int lane = threadIdx.x & 31;
    if (warp >= total) return;
    int h = warp / N_NODES;
    const float* row = Wh + (long)warp * D;
    const float* ah  = a + h * 2 * D;
    float s1 = 0.f, s2 = 0.f;
    for (int d = lane; d < D; d += 32) {
        float v = row[d];
        s1 += v * ah[d];
        s2 += v * ah[D + d];
    }
    #pragma unroll
    for (int o = 16; o; o >>= 1) {
        s1 += __shfl_xor_sync(0xffffffffu, s1, o);
        s2 += __shfl_xor_sync(0xffffffffu, s2, o);
    }
    if (lane == 0) { f1[warp] = s1; f2[warp] = s2; }
}

// ---------------- sparse masked softmax + aggregate + ELU ----------------
// block = D threads, grid = (N_NODES, nHeads). One block per (row i, head h).
template <int D>
__global__ void gat_atten(const float* __restrict__ Wh,
                          const float* __restrict__ f1v, const float* __restrict__ f2v,
                          const int* __restrict__ cols, const int* __restrict__ degs,
                          float* __restrict__ out,
                          long whHeadStride, long outHeadStride, long outRowStride)
{
    __shared__ int   s_cols[MAXD];
    __shared__ float s_w[MAXD];
    __shared__ float red[D];

    int i = blockIdx.x;
    int h = blockIdx.y;
    int tid = threadIdx.x;
    int deg = degs[i];
    const int* crow = cols + (size_t)i * MAXD;
    const float fi = f1v[h * N_NODES + i];
    const float* f2h = f2v + h * N_NODES;

    // pass 1: e = leaky_relu(f1_i + f2_j), track max
    float lmax = -INFINITY;
    for (int k = tid; k < deg; k += D) {
        int c = crow[k];
        s_cols[k] = c;
        float e = fi + f2h[c];
        e = e > 0.f ? e : 0.2f * e;
        s_w[k] = e;
        lmax = fmaxf(lmax, e);
    }
    red[tid] = lmax;
    __syncthreads();
    #pragma unroll
    for (int s = D / 2; s > 0; s >>= 1) {
        if (tid < s) red[tid] = fmaxf(red[tid], red[tid + s]);
        __syncthreads();
    }
    float m = red[0];
    __syncthreads();

    // pass 2: exp and sum
    float lsum = 0.f;
    for (int k = tid; k < deg; k += D) {
        float w = expf(s_w[k] - m);
        s_w[k] = w;
        lsum += w;
    }
    red[tid] = lsum;
    __syncthreads();
    #pragma unroll
    for (int s = D / 2; s > 0; s >>= 1) {
        if (tid < s) red[tid] += red[tid + s];
        __syncthreads();
    }
    float inv = 1.0f / red[0];

    // pass 3: gather-aggregate Wh rows (coalesced across f = tid)
    const float* whh = Wh + (long)h * whHeadStride;
    float a0 = 0.f, a1 = 0.f, a2 = 0.f, a3 = 0.f;
    int k = 0;
    for (; k + 4 <= deg; k += 4) {
        a0 += s_w[k + 0] * __ldg(whh + (long)s_cols[k + 0] * D + tid);
        a1 += s_w[k + 1] * __ldg(whh + (long)s_cols[k + 1] * D + tid);
        a2 += s_w[k + 2] * __ldg(whh + (long)s_cols[k + 2] * D + tid);
        a3 += s_w[k + 3] * __ldg(whh + (long)s_cols[k + 3] * D + tid);
    }
    for (; k < deg; k++)
        a0 += s_w[k] * __ldg(whh + (long)s_cols[k] * D + tid);

    float v = (a0 + a1 + a2 + a3) * inv;
    v = v > 0.f ? v : expm1f(v);   // ELU (matches jax.nn.elu exactly)
    out[(long)h * outHeadStride + (long)i * outRowStride + tid] = v;
}

// ---------------- launch ----------------
extern "C" void kernel_launch(void* const* d_in, const int* in_sizes, int n_in,
                              void* d_out, int out_size)
{
    const float* x     = (const float*)d_in[0];
    const float* adj   = (const float*)d_in[1];
    const int*   obs   = (const int*)  d_in[2];
    // d_in[3] = s_mat (unused, method='base')
    const float* theta = (const float*)d_in[4];
    const float* W0    = (const float*)d_in[5];
    const float* a0    = (const float*)d_in[6];
    const float* W1    = (const float*)d_in[7];
    const float* a1    = (const float*)d_in[8];
    const float* Wo    = (const float*)d_in[9];
    const float* ao    = (const float*)d_in[10];
    float* out = (float*)d_out;

    float *ph, *pWh0, *pact0, *pWh1, *phc, *pWhc, *pf1, *pf2;
    int *pcols, *pdeg;
    cudaGetSymbolAddress((void**)&ph,    g_h);
    cudaGetSymbolAddress((void**)&pcols, g_cols);
    cudaGetSymbolAddress((void**)&pdeg,  g_deg);
    cudaGetSymbolAddress((void**)&pWh0,  g_Wh0);
    cudaGetSymbolAddress((void**)&pact0, g_act0);
    cudaGetSymbolAddress((void**)&pWh1,  g_Wh1);
    cudaGetSymbolAddress((void**)&phc,   g_hc);
    cudaGetSymbolAddress((void**)&pWhc,  g_Whc);
    cudaGetSymbolAddress((void**)&pf1,   g_f1);
    cudaGetSymbolAddress((void**)&pf2,   g_f2);

    // 0) merge state + adjacency structure
    merge_state<<<(N_NODES * FEAT / 4 + 255) / 256, 256>>>(x, obs, theta, ph);
    build_ell<<<N_NODES, 256>>>(adj, pcols, pdeg);

    // 1) layer 0: Wh0 = h @ W0[h]   (A shared across heads: sA = 0)
    sgemm_bat<128, 128, 16, 8, 8><<<dim3(N_NODES / 128, 1, HEADS), 256>>>(
        ph, W0, pWh0, N_NODES, DH, FEAT, 0L, (long)FEAT * DH, (long)N_NODES * DH);
    calc_f12<DH><<<(N_NODES * HEADS) / 8, 256>>>(pWh0, a0, pf1, pf2, N_NODES * HEADS);
    gat_atten<DH><<<dim3(N_NODES, HEADS), DH>>>(
        pWh0, pf1, pf2, pcols, pdeg, pact0,
        (long)N_NODES * DH, (long)N_NODES * DH, (long)DH);

    // 2) layer 1: Wh1 = act0[h] @ W1[h]
    sgemm_bat<128, 128, 16, 8, 8><<<dim3(N_NODES / 128, 1, HEADS), 256>>>(
        pact0, W1, pWh1, N_NODES, DH, DH,
        (long)N_NODES * DH, (long)DH * DH, (long)N_NODES * DH);
    calc_f12<DH><<<(N_NODES * HEADS) / 8, 256>>>(pWh1, a1, pf1, pf2, N_NODES * HEADS);
    // write head-concat layout hc[i][h*DH + f]
    gat_atten<DH><<<dim3(N_NODES, HEADS), DH>>>(
        pWh1, pf1, pf2, pcols, pdeg, phc,
        (long)N_NODES * DH, (long)DH, (long)HEADS * DH);

    // 3) output layer: Whc = hc @ Wo, single head, final ELU fused
    sgemm_bat<64, 64, 16, 4, 4><<<dim3(N_NODES / 64, 1, 1), 256>>>(
        phc, Wo, pWhc, N_NODES, DOUT, HEADS * DH, 0L, 0L, 0L);
    calc_f12<DOUT><<<N_NODES / 8, 256>>>(pWhc, ao, pf1, pf2, N_NODES);
    gat_atten<DOUT><<<dim3(N_NODES, 1), DOUT>>>(
        pWhc, pf1, pf2, pcols, pdeg, out, 0L, 0L, (long)DOUT);
}

// round 6
// speedup vs baseline: 1.6122x; 1.6122x over previous
#include <cuda_runtime.h>
#include <cuda_bf16.h>
#include <math.h>

#define N_NODES 3072
#define FEAT    256
#define HEADS   8
#define DH      128
#define DOUT    64
#define MAXD    512

// ---------------- device scratch ----------------
__device__ float g_h[N_NODES * FEAT];
__device__ int   g_cols[N_NODES * MAXD];
__device__ int   g_deg[N_NODES];
__device__ float g_Wh[HEADS * N_NODES * DH];          // fp32 Wh (layer0, then reused meaning)
__device__ __nv_bfloat162 g_Whb[HEADS * N_NODES * (DH/2)]; // bf16 copy for gather
__device__ float g_act0[HEADS * N_NODES * DH];
__device__ float g_hc[N_NODES * HEADS * DH];
__device__ float g_Whc[N_NODES * DOUT];
__device__ float g_f1[HEADS * N_NODES];
__device__ float g_f2[HEADS * N_NODES];

// ---------------- mergeState ----------------
__global__ void merge_state(const float* __restrict__ x, const int* __restrict__ obs,
                            const float* __restrict__ theta, float* __restrict__ h)
{
    int idx = blockIdx.x * blockDim.x + threadIdx.x;
    const int total = N_NODES * FEAT / 4;
    if (idx >= total) return;
    int row = idx / (FEAT / 4);
    float4 v = reinterpret_cast<const float4*>(x)[idx];
    if (obs[row] == 1) {
        float4 t = reinterpret_cast<const float4*>(theta)[idx % (FEAT / 4)];
        v.x += t.x; v.y += t.y; v.z += t.z; v.w += t.w;
    }
    reinterpret_cast<float4*>(h)[idx] = v;
}

// ---------------- build ELL adjacency ----------------
__global__ void build_ell(const float* __restrict__ adj, int* __restrict__ cols,
                          int* __restrict__ degs)
{
    int i = blockIdx.x;
    __shared__ int cnt;
    if (threadIdx.x == 0) cnt = 0;
    __syncthreads();
    const float* row = adj + (size_t)i * N_NODES;
    for (int j = threadIdx.x; j < N_NODES; j += blockDim.x) {
        if (row[j] > 0.f) {
            int p = atomicAdd(&cnt, 1);
            if (p < MAXD) cols[i * MAXD + p] = j;
        }
    }
    __syncthreads();
    if (threadIdx.x == 0) degs[i] = cnt < MAXD ? cnt : MAXD;
}

// ---------------- tiled fp32 batched GEMM with fused f1/f2 epilogue ----------------
// Requires BN == full output width Nn (each block owns complete rows).
// Optionally also writes a bf16 copy of C for the gather kernel.
template <int BM, int BN, int BK, int TM, int TN, bool BF16OUT>
__global__ __launch_bounds__(256)
void sgemm_fused(const float* __restrict__ A, const float* __restrict__ B,
                 float* __restrict__ C, __nv_bfloat162* __restrict__ Cb,
                 const float* __restrict__ avec,
                 float* __restrict__ f1, float* __restrict__ f2,
                 int K, long sA, long sB, long sC)
{
    constexpr int TX = BN / TN;              // 16 for both configs
    constexpr int TY = BM / TM;
    constexpr int NT = TX * TY;              // 256
    static_assert(TX == 16, "epilogue reduction assumes TX=16");
    __shared__ float As[BK][BM];
    __shared__ float Bs[BK][BN];
    __shared__ float a1s[BN], a2s[BN];

    int z = blockIdx.z;
    A += (long)z * sA;  B += (long)z * sB;
    int bm = blockIdx.x;
    int tid = threadIdx.x;
    int tx = tid % TX, ty = tid / TX;

    if (tid < BN)      a1s[tid] = avec[z * 2 * BN + tid];
    else if (tid < 2 * BN) a2s[tid - BN] = avec[z * 2 * BN + tid];

    float acc[TM][TN];
    #pragma unroll
    for (int m = 0; m < TM; m++)
        #pragma unroll
        for (int n = 0; n < TN; n++) acc[m][n] = 0.f;

    constexpr int A_UNITS = BM * BK / 4;
    constexpr int B_UNITS = BK * BN / 4;

    for (int k0 = 0; k0 < K; k0 += BK) {
        for (int u = tid; u < A_UNITS; u += NT) {
            int r  = u / (BK / 4);
            int c4 = (u % (BK / 4)) * 4;
            float4 v = *reinterpret_cast<const float4*>(
                A + (long)(bm * BM + r) * K + k0 + c4);
            As[c4 + 0][r] = v.x; As[c4 + 1][r] = v.y;
            As[c4 + 2][r] = v.z; As[c4 + 3][r] = v.w;
        }
        for (int u = tid; u < B_UNITS; u += NT) {
            int r  = u / (BN / 4);
            int c4 = (u % (BN / 4)) * 4;
            *reinterpret_cast<float4*>(&Bs[r][c4]) =
                *reinterpret_cast<const float4*>(B + (long)(k0 + r) * BN + c4);
        }
        __syncthreads();
        #pragma unroll
        for (int kk = 0; kk < BK; kk++) {
            float ra[TM], rb[TN];
            #pragma unroll
            for (int m = 0; m < TM; m++) ra[m] = As[kk][ty * TM + m];
            #pragma unroll
            for (int n = 0; n < TN; n++) rb[n] = Bs[kk][tx * TN + n];
            #pragma unroll
            for (int m = 0; m < TM; m++)
                #pragma unroll
                for (int n = 0; n < TN; n++) acc[m][n] += ra[m] * rb[n];
        }
        __syncthreads();
    }

    #pragma unroll
    for (int m = 0; m < TM; m++) {
        int row = bm * BM + ty * TM + m;
        float* crow = C + (long)z * sC + (long)row * BN + tx * TN;
        #pragma unroll
        for (int n = 0; n < TN; n++) crow[n] = acc[m][n];

        if (BF16OUT) {
            __nv_bfloat162 pk[TN / 2];
            #pragma unroll
            for (int n = 0; n < TN; n += 2)
                pk[n / 2] = __floats2bfloat162_rn(acc[m][n], acc[m][n + 1]);
            __nv_bfloat162* brow = Cb + ((long)z * N_NODES + row) * (BN / 2) + tx * (TN / 2);
            #pragma unroll
            for (int n2 = 0; n2 < TN / 2; n2++) brow[n2] = pk[n2];
        }

        // fused f1/f2: exact row-dot with a (rows are fully owned by this block)
        float s1 = 0.f, s2 = 0.f;
        #pragma unroll
        for (int n = 0; n < TN; n++) {
            int c = tx * TN + n;
            s1 += acc[m][n] * a1s[c];
            s2 += acc[m][n] * a2s[c];
        }
        #pragma unroll
        for (int o = 8; o; o >>= 1) {
            s1 += __shfl_xor_sync(0xffffffffu, s1, o, 16);
            s2 += __shfl_xor_sync(0xffffffffu, s2, o, 16);
        }
        if (tx == 0) {
            f1[z * N_NODES + row] = s1;
            f2[z * N_NODES + row] = s2;
        }
    }
}

// ---------------- sparse softmax + bf16 gather-aggregate + ELU (DH=128) ----------------
// block = 64 threads (one bf162 lane each), grid = (N_NODES, HEADS)
__global__ __launch_bounds__(64)
void gat_atten_bf(const __nv_bfloat162* __restrict__ Whb,
                  const float* __restrict__ f1v, const float* __restrict__ f2v,
                  const int* __restrict__ cols, const int* __restrict__ degs,
                  float* __restrict__ out,
                  long outHeadStride, long outRowStride)
{
    __shared__ int   s_cols[MAXD];
    __shared__ float s_w[MAXD];
    __shared__ float red[64];

    int i = blockIdx.x, h = blockIdx.y, t = threadIdx.x;
    int deg = degs[i];
    const int* crow = cols + (size_t)i * MAXD;
    const float fi = f1v[h * N_NODES + i];
    const float* f2h = f2v + h * N_NODES;

    float lmax = -INFINITY;
    for (int k = t; k < deg; k += 64) {
        int c = crow[k];
        s_cols[k] = c;
        float e = fi + f2h[c];
        e = e > 0.f ? e : 0.2f * e;
        s_w[k] = e;
        lmax = fmaxf(lmax, e);
    }
    red[t] = lmax;
    __syncthreads();
    #pragma unroll
    for (int s = 32; s > 0; s >>= 1) {
        if (t < s) red[t] = fmaxf(red[t], red[t + s]);
        __syncthreads();
    }
    float m = red[0];
    __syncthreads();

    float lsum = 0.f;
    for (int k = t; k < deg; k += 64) {
        float w = expf(s_w[k] - m);
        s_w[k] = w;
        lsum += w;
    }
    red[t] = lsum;
    __syncthreads();
    #pragma unroll
    for (int s = 32; s > 0; s >>= 1) {
        if (t < s) red[t] += red[t + s];
        __syncthreads();
    }
    float inv = 1.0f / red[0];

    const __nv_bfloat162* whh = Whb + (long)h * N_NODES * (DH / 2);
    float ax = 0.f, ay = 0.f, bx = 0.f, by = 0.f;
    int k = 0;
    for (; k + 4 <= deg; k += 4) {
        __nv_bfloat162 v0 = whh[(long)s_cols[k + 0] * (DH / 2) + t];
        __nv_bfloat162 v1 = whh[(long)s_cols[k + 1] * (DH / 2) + t];
        __nv_bfloat162 v2 = whh[(long)s_cols[k + 2] * (DH / 2) + t];
        __nv_bfloat162 v3 = whh[(long)s_cols[k + 3] * (DH / 2) + t];
        float w0 = s_w[k + 0], w1 = s_w[k + 1], w2 = s_w[k + 2], w3 = s_w[k + 3];
        ax += w0 * __low2float(v0); ay += w0 * __high2float(v0);
        bx += w1 * __low2float(v1); by += w1 * __high2float(v1);
        ax += w2 * __low2float(v2); ay += w2 * __high2float(v2);
        bx += w3 * __low2float(v3); by += w3 * __high2float(v3);
    }
    for (; k < deg; k++) {
        __nv_bfloat162 v0 = whh[(long)s_cols[k] * (DH / 2) + t];
        float w0 = s_w[k];
        ax += w0 * __low2float(v0); ay += w0 * __high2float(v0);
    }
    float vx = (ax + bx) * inv;
    float vy = (ay + by) * inv;
    vx = vx > 0.f ? vx : expm1f(vx);
    vy = vy > 0.f ? vy : expm1f(vy);
    float* orow = out + (long)h * outHeadStride + (long)i * outRowStride;
    orow[2 * t]     = vx;
    orow[2 * t + 1] = vy;
}

// ---------------- fp32 gather for output layer (D=64) ----------------
__global__ __launch_bounds__(64)
void gat_atten_f32(const float* __restrict__ Wh,
                   const float* __restrict__ f1v, const float* __restrict__ f2v,
                   const int* __restrict__ cols, const int* __restrict__ degs,
                   float* __restrict__ out)
{
    __shared__ int   s_cols[MAXD];
    __shared__ float s_w[MAXD];
    __shared__ float red[64];

    int i = blockIdx.x, t = threadIdx.x;
    int deg = degs[i];
    const int* crow = cols + (size_t)i * MAXD;
    const float fi = f1v[i];

    float lmax = -INFINITY;
    for (int k = t; k < deg; k += 64) {
        int c = crow[k];
        s_cols[k] = c;
        float e = fi + f2v[c];
        e = e > 0.f ? e : 0.2f * e;
        s_w[k] = e;
        lmax = fmaxf(lmax, e);
    }
    red[t] = lmax;
    __syncthreads();
    #pragma unroll
    for (int s = 32; s > 0; s >>= 1) {
        if (t < s) red[t] = fmaxf(red[t], red[t + s]);
        __syncthreads();
    }
    float m = red[0];
    __syncthreads();

    float lsum = 0.f;
    for (int k = t; k < deg; k += 64) {
        float w = expf(s_w[k] - m);
        s_w[k] = w;
        lsum += w;
    }
    red[t] = lsum;
    __syncthreads();
    #pragma unroll
    for (int s = 32; s > 0; s >>= 1) {
        if (t < s) red[t] += red[t + s];
        __syncthreads();
    }
    float inv = 1.0f / red[0];

    float a0 = 0.f, a1 = 0.f, a2 = 0.f, a3 = 0.f;
    int k = 0;
    for (; k + 4 <= deg; k += 4) {
        a0 += s_w[k + 0] * __ldg(Wh + (long)s_cols[k + 0] * DOUT + t);
        a1 += s_w[k + 1] * __ldg(Wh + (long)s_cols[k + 1] * DOUT + t);
        a2 += s_w[k + 2] * __ldg(Wh + (long)s_cols[k + 2] * DOUT + t);
        a3 += s_w[k + 3] * __ldg(Wh + (long)s_cols[k + 3] * DOUT + t);
    }
    for (; k < deg; k++)
        a0 += s_w[k] * __ldg(Wh + (long)s_cols[k] * DOUT + t);

    float v = (a0 + a1 + a2 + a3) * inv;
    v = v > 0.f ? v : expm1f(v);
    out[(long)i * DOUT + t] = v;
}

// ---------------- launch ----------------
extern "C" void kernel_launch(void* const* d_in, const int* in_sizes, int n_in,
                              void* d_out, int out_size)
{
    const float* x     = (const float*)d_in[0];
    const float* adj   = (const float*)d_in[1];
    const int*   obs   = (const int*)  d_in[2];
    const float* theta = (const float*)d_in[4];
    const float* W0    = (const float*)d_in[5];
    const float* a0    = (const float*)d_in[6];
    const float* W1    = (const float*)d_in[7];
    const float* a1    = (const float*)d_in[8];
    const float* Wo    = (const float*)d_in[9];
    const float* ao    = (const float*)d_in[10];
    float* out = (float*)d_out;

    float *ph, *pWh, *pact0, *phc, *pWhc, *pf1, *pf2;
    __nv_bfloat162* pWhb;
    int *pcols, *pdeg;
    cudaGetSymbolAddress((void**)&ph,    g_h);
    cudaGetSymbolAddress((void**)&pcols, g_cols);
    cudaGetSymbolAddress((void**)&pdeg,  g_deg);
    cudaGetSymbolAddress((void**)&pWh,   g_Wh);
    cudaGetSymbolAddress((void**)&pWhb,  g_Whb);
    cudaGetSymbolAddress((void**)&pact0, g_act0);
    cudaGetSymbolAddress((void**)&phc,   g_hc);
    cudaGetSymbolAddress((void**)&pWhc,  g_Whc);
    cudaGetSymbolAddress((void**)&pf1,   g_f1);
    cudaGetSymbolAddress((void**)&pf2,   g_f2);

    merge_state<<<(N_NODES * FEAT / 4 + 255) / 256, 256>>>(x, obs, theta, ph);
    build_ell<<<N_NODES, 256>>>(adj, pcols, pdeg);

    // layer 0: Wh = h @ W0[h], fused f1/f2 + bf16 copy
    sgemm_fused<128, 128, 16, 8, 8, true><<<dim3(N_NODES / 128, 1, HEADS), 256>>>(
        ph, W0, pWh, pWhb, a0, pf1, pf2, FEAT, 0L, (long)FEAT * DH, (long)N_NODES * DH);
    gat_atten_bf<<<dim3(N_NODES, HEADS), 64>>>(
        pWhb, pf1, pf2, pcols, pdeg, pact0, (long)N_NODES * DH, (long)DH);

    // layer 1: Wh = act0[h] @ W1[h]
    sgemm_fused<128, 128, 16, 8, 8, true><<<dim3(N_NODES / 128, 1, HEADS), 256>>>(
        pact0, W1, pWh, pWhb, a1, pf1, pf2, DH,
        (long)N_NODES * DH, (long)DH * DH, (long)N_NODES * DH);
    gat_atten_bf<<<dim3(N_NODES, HEADS), 64>>>(
        pWhb, pf1, pf2, pcols, pdeg, phc, (long)DH, (long)HEADS * DH);

    // output layer: Whc = hc @ Wo (fp32 gather, final ELU fused)
    sgemm_fused<128, 64, 16, 8, 4, false><<<dim3(N_NODES / 128, 1, 1), 256>>>(
        phc, Wo, pWhc, nullptr, ao, pf1, pf2, HEADS * DH, 0L, 0L, 0L);
    gat_atten_f32<<<N_NODES, 64>>>(pWhc, pf1, pf2, pcols, pdeg, out);
}

// round 8
// speedup vs baseline: 1.6715x; 1.0368x over previous
#include <cuda_runtime.h>
#include <cuda_bf16.h>
#include <math.h>

#define N_NODES 3072
#define FEAT    256
#define HEADS   8
#define DH      128
#define DOUT    64
#define MAXD    512

// ---------------- device scratch ----------------
__device__ float g_h[N_NODES * FEAT];
__device__ int   g_cols[N_NODES * MAXD];
__device__ int   g_deg[N_NODES];
__device__ float g_Wh[HEADS * N_NODES * DH];
__device__ __nv_bfloat162 g_Whb[HEADS * N_NODES * (DH/2)];
__device__ float g_act0[HEADS * N_NODES * DH];
__device__ float g_hc[N_NODES * HEADS * DH];
__device__ float g_Whc[N_NODES * DOUT];
__device__ float g_f1[HEADS * N_NODES];
__device__ float g_f2[HEADS * N_NODES];

// ---------------- packed f32x2 helpers (sm_103a FFMA2) ----------------
__device__ __forceinline__ unsigned long long pk2(unsigned lo, unsigned hi) {
    unsigned long long r;
    asm("mov.b64 %0,{%1,%2};" : "=l"(r) : "r"(lo), "r"(hi));
    return r;
}
__device__ __forceinline__ void upk2(unsigned long long v, float& a, float& b) {
    unsigned lo, hi;
    asm("mov.b64 {%0,%1},%2;" : "=r"(lo), "=r"(hi) : "l"(v));
    a = __int_as_float(lo); b = __int_as_float(hi);
}
__device__ __forceinline__ unsigned long long ffma2(unsigned long long a,
                                                    unsigned long long b,
                                                    unsigned long long c) {
    unsigned long long d;
    asm("fma.rn.f32x2 %0,%1,%2,%3;" : "=l"(d) : "l"(a), "l"(b), "l"(c));
    return d;
}

// ---------------- mergeState ----------------
__global__ void merge_state(const float* __restrict__ x, const int* __restrict__ obs,
                            const float* __restrict__ theta, float* __restrict__ h)
{
    int idx = blockIdx.x * blockDim.x + threadIdx.x;
    const int total = N_NODES * FEAT / 4;
    if (idx >= total) return;
    int row = idx / (FEAT / 4);
    float4 v = reinterpret_cast<const float4*>(x)[idx];
    if (obs[row] == 1) {
        float4 t = reinterpret_cast<const float4*>(theta)[idx % (FEAT / 4)];
        v.x += t.x; v.y += t.y; v.z += t.z; v.w += t.w;
    }
    reinterpret_cast<float4*>(h)[idx] = v;
}

// ---------------- build ELL adjacency ----------------
__global__ void build_ell(const float* __restrict__ adj, int* __restrict__ cols,
                          int* __restrict__ degs)
{
    int i = blockIdx.x;
    __shared__ int cnt;
    if (threadIdx.x == 0) cnt = 0;
    __syncthreads();
    const float* row = adj + (size_t)i * N_NODES;
    for (int j = threadIdx.x; j < N_NODES; j += blockDim.x) {
        if (row[j] > 0.f) {
            int p = atomicAdd(&cnt, 1);
            if (p < MAXD) cols[i * MAXD + p] = j;
        }
    }
    __syncthreads();
    if (threadIdx.x == 0) degs[i] = cnt < MAXD ? cnt : MAXD;
}

// ---------------- tiled fp32 batched GEMM with fused f1/f2 epilogue ----------------
template <int BM, int BN, int BK, int TM, int TN, bool BF16OUT>
__global__ __launch_bounds__(256)
void sgemm_fused(const float* __restrict__ A, const float* __restrict__ B,
                 float* __restrict__ C, __nv_bfloat162* __restrict__ Cb,
                 const float* __restrict__ avec,
                 float* __restrict__ f1, float* __restrict__ f2,
                 int K, long sA, long sB, long sC)
{
    constexpr int TX = BN / TN;
    constexpr int TY = BM / TM;
    constexpr int NT = TX * TY;
    static_assert(TX == 16, "epilogue reduction assumes TX=16");
    __shared__ float As[BK][BM];
    __shared__ float Bs[BK][BN];
    __shared__ float a1s[BN], a2s[BN];

    int z = blockIdx.z;
    A += (long)z * sA;  B += (long)z * sB;
    int bm = blockIdx.x;
    int tid = threadIdx.x;
    int tx = tid % TX, ty = tid / TX;

    if (tid < BN)          a1s[tid] = avec[z * 2 * BN + tid];
    else if (tid < 2 * BN) a2s[tid - BN] = avec[z * 2 * BN + tid];

    float acc[TM][TN];
    #pragma unroll
    for (int m = 0; m < TM; m++)
        #pragma unroll
        for (int n = 0; n < TN; n++) acc[m][n] = 0.f;

    constexpr int A_UNITS = BM * BK / 4;
    constexpr int B_UNITS = BK * BN / 4;

    for (int k0 = 0; k0 < K; k0 += BK) {
        for (int u = tid; u < A_UNITS; u += NT) {
            int r  = u / (BK / 4);
            int c4 = (u % (BK / 4)) * 4;
            float4 v = *reinterpret_cast<const float4*>(
                A + (long)(bm * BM + r) * K + k0 + c4);
            As[c4 + 0][r] = v.x; As[c4 + 1][r] = v.y;
            As[c4 + 2][r] = v.z; As[c4 + 3][r] = v.w;
        }
        for (int u = tid; u < B_UNITS; u += NT) {
            int r  = u / (BN / 4);
            int c4 = (u % (BN / 4)) * 4;
            *reinterpret_cast<float4*>(&Bs[r][c4]) =
                *reinterpret_cast<const float4*>(B + (long)(k0 + r) * BN + c4);
        }
        __syncthreads();
        #pragma unroll
        for (int kk = 0; kk < BK; kk++) {
            float ra[TM], rb[TN];
            #pragma unroll
            for (int m = 0; m < TM; m++) ra[m] = As[kk][ty * TM + m];
            #pragma unroll
            for (int n = 0; n < TN; n++) rb[n] = Bs[kk][tx * TN + n];
            #pragma unroll
            for (int m = 0; m < TM; m++)
                #pragma unroll
                for (int n = 0; n < TN; n++) acc[m][n] += ra[m] * rb[n];
        }
        __syncthreads();
    }

    #pragma unroll
    for (int m = 0; m < TM; m++) {
        int row = bm * BM + ty * TM + m;
        float* crow = C + (long)z * sC + (long)row * BN + tx * TN;
        #pragma unroll
        for (int n = 0; n < TN; n++) crow[n] = acc[m][n];

        if (BF16OUT) {
            __nv_bfloat162 pk[TN / 2];
            #pragma unroll
            for (int n = 0; n < TN; n += 2)
                pk[n / 2] = __floats2bfloat162_rn(acc[m][n], acc[m][n + 1]);
            __nv_bfloat162* brow = Cb + ((long)z * N_NODES + row) * (BN / 2) + tx * (TN / 2);
            #pragma unroll
            for (int n2 = 0; n2 < TN / 2; n2++) brow[n2] = pk[n2];
        }

        float s1 = 0.f, s2 = 0.f;
        #pragma unroll
        for (int n = 0; n < TN; n++) {
            int c = tx * TN + n;
            s1 += acc[m][n] * a1s[c];
            s2 += acc[m][n] * a2s[c];
        }
        #pragma unroll
        for (int o = 8; o; o >>= 1) {
            s1 += __shfl_xor_sync(0xffffffffu, s1, o, 16);
            s2 += __shfl_xor_sync(0xffffffffu, s2, o, 16);
        }
        if (tx == 0) {
            f1[z * N_NODES + row] = s1;
            f2[z * N_NODES + row] = s2;
        }
    }
}

// ---------------- sparse softmax + bf16 gather (DH=128) ----------------
// 128 threads = 4 warps; each warp covers a full 256B row per edge (LDG.64/lane).
__global__ __launch_bounds__(128)
void gat_atten_bf(const __nv_bfloat162* __restrict__ Whb,
                  const float* __restrict__ f1v, const float* __restrict__ f2v,
                  const int* __restrict__ cols, const int* __restrict__ degs,
                  float* __restrict__ out,
                  long outHeadStride, long outRowStride)
{
    __shared__ int   s_off[MAXD];    // byte offset of neighbor row (c << 8)
    __shared__ float s_w[MAXD];
    __shared__ float red[128];
    __shared__ float part[4][DH];

    int i = blockIdx.x, h = blockIdx.y, t = threadIdx.x;
    int wid = t >> 5, lane = t & 31;
    int deg = degs[i];
    const int* crow = cols + (size_t)i * MAXD;
    const float fi = f1v[h * N_NODES + i];
    const float* f2h = f2v + h * N_NODES;

    // pass 1: e = leaky_relu(f1_i + f2_j), max
    float lmax = -INFINITY;
    for (int k = t; k < deg; k += 128) {
        int c = crow[k];
        s_off[k] = c << 8;           // c * DH * sizeof(bf16) = c * 256
        float e = fi + f2h[c];
        e = e > 0.f ? e : 0.2f * e;
        s_w[k] = e;
        lmax = fmaxf(lmax, e);
    }
    red[t] = lmax;
    __syncthreads();
    #pragma unroll
    for (int s = 64; s > 0; s >>= 1) {
        if (t < s) red[t] = fmaxf(red[t], red[t + s]);
        __syncthreads();
    }
    float m = red[0];
    __syncthreads();

    // pass 2: exp + sum
    float lsum = 0.f;
    for (int k = t; k < deg; k += 128) {
        float w = __expf(s_w[k] - m);
        s_w[k] = w;
        lsum += w;
    }
    red[t] = lsum;
    __syncthreads();
    #pragma unroll
    for (int s = 64; s > 0; s >>= 1) {
        if (t < s) red[t] += red[t + s];
        __syncthreads();
    }
    float inv = 1.0f / red[0];
    __syncthreads();

    // pass 3: warp-per-edge gather with FFMA2
    const char* base = (const char*)(Whb + (long)h * N_NODES * (DH / 2)) + lane * 8;
    unsigned long long acc0 = 0ULL, acc1 = 0ULL;
    #pragma unroll 2
    for (int k = wid; k < deg; k += 4) {
        uint2 u = *(const uint2*)(base + s_off[k]);
        unsigned wb = __float_as_uint(s_w[k]);
        unsigned long long wp = pk2(wb, wb);
        acc0 = ffma2(pk2(u.x << 16, u.x & 0xffff0000u), wp, acc0);
        acc1 = ffma2(pk2(u.y << 16, u.y & 0xffff0000u), wp, acc1);
    }
    float f0, f1x, f2x, f3;
    upk2(acc0, f0, f1x);
    upk2(acc1, f2x, f3);
    part[wid][4 * lane + 0] = f0;
    part[wid][4 * lane + 1] = f1x;
    part[wid][4 * lane + 2] = f2x;
    part[wid][4 * lane + 3] = f3;
    __syncthreads();

    float v = (part[0][t] + part[1][t] + part[2][t] + part[3][t]) * inv;
    v = v > 0.f ? v : expm1f(v);
    out[(long)h * outHeadStride + (long)i * outRowStride + t] = v;
}

// ---------------- fp32 gather for output layer (D=64) ----------------
__global__ __launch_bounds__(128)
void gat_atten_f32(const float* __restrict__ Wh,
                   const float* __restrict__ f1v, const float* __restrict__ f2v,
                   const int* __restrict__ cols, const int* __restrict__ degs,
                   float* __restrict__ out)
{
    __shared__ int   s_off[MAXD];
    __shared__ float s_w[MAXD];
    __shared__ float red[128];
    __shared__ float part[4][DOUT];

    int i = blockIdx.x, t = threadIdx.x;
    int wid = t >> 5, lane = t & 31;
    int deg = degs[i];
    const int* crow = cols + (size_t)i * MAXD;
    const float fi = f1v[i];

    float lmax = -INFINITY;
    for (int k = t; k < deg; k += 128) {
        int c = crow[k];
        s_off[k] = c << 8;           // c * DOUT * sizeof(float) = c * 256
        float e = fi + f2v[c];
        e = e > 0.f ? e : 0.2f * e;
        s_w[k] = e;
        lmax = fmaxf(lmax, e);
    }
    red[t] = lmax;
    __syncthreads();
    #pragma unroll
    for (int s = 64; s > 0; s >>= 1) {
        if (t < s) red[t] = fmaxf(red[t], red[t + s]);
        __syncthreads();
    }
    float m = red[0];
    __syncthreads();

    float lsum = 0.f;
    for (int k = t; k < deg; k += 128) {
        float w = __expf(s_w[k] - m);
        s_w[k] = w;
        lsum += w;
    }
    red[t] = lsum;
    __syncthreads();
    #pragma unroll
    for (int s = 64; s > 0; s >>= 1) {
        if (t < s) red[t] += red[t + s];
        __syncthreads();
    }
    float inv = 1.0f / red[0];
    __syncthreads();

    // warp-per-edge: 32 lanes x float2 = 256B row
    const char* base = (const char*)Wh + lane * 8;
    unsigned long long acc = 0ULL;
    #pragma unroll 2
    for (int k = wid; k < deg; k += 4) {
        unsigned long long u = *(const unsigned long long*)(base + s_off[k]);
        unsigned wb = __float_as_uint(s_w[k]);
        acc = ffma2(u, pk2(wb, wb), acc);
    }
    float f0, f1x;
    upk2(acc, f0, f1x);
    part[wid][2 * lane + 0] = f0;
    part[wid][2 * lane + 1] = f1x;
    __syncthreads();

    if (t < DOUT) {
        float v = (part[0][t] + part[1][t] + part[2][t] + part[3][t]) * inv;
        v = v > 0.f ? v : expm1f(v);
        out[(long)i * DOUT + t] = v;
    }
}

// ---------------- launch ----------------
extern "C" void kernel_launch(void* const* d_in, const int* in_sizes, int n_in,
                              void* d_out, int out_size)
{
    const float* x     = (const float*)d_in[0];
    const float* adj   = (const float*)d_in[1];
    const int*   obs   = (const int*)  d_in[2];
    const float* theta = (const float*)d_in[4];
    const float* W0    = (const float*)d_in[5];
    const float* a0    = (const float*)d_in[6];
    const float* W1    = (const float*)d_in[7];
    const float* a1    = (const float*)d_in[8];
    const float* Wo    = (const float*)d_in[9];
    const float* ao    = (const float*)d_in[10];
    float* out = (float*)d_out;

    float *ph, *pWh, *pact0, *phc, *pWhc, *pf1, *pf2;
    __nv_bfloat162* pWhb;
    int *pcols, *pdeg;
    cudaGetSymbolAddress((void**)&ph,    g_h);
    cudaGetSymbolAddress((void**)&pcols, g_cols);
    cudaGetSymbolAddress((void**)&pdeg,  g_deg);
    cudaGetSymbolAddress((void**)&pWh,   g_Wh);
    cudaGetSymbolAddress((void**)&pWhb,  g_Whb);
    cudaGetSymbolAddress((void**)&pact0, g_act0);
    cudaGetSymbolAddress((void**)&phc,   g_hc);
    cudaGetSymbolAddress((void**)&pWhc,  g_Whc);
    cudaGetSymbolAddress((void**)&pf1,   g_f1);
    cudaGetSymbolAddress((void**)&pf2,   g_f2);

    merge_state<<<(N_NODES * FEAT / 4 + 255) / 256, 256>>>(x, obs, theta, ph);
    build_ell<<<N_NODES, 256>>>(adj, pcols, pdeg);

    // layer 0
    sgemm_fused<128, 128, 16, 8, 8, true><<<dim3(N_NODES / 128, 1, HEADS), 256>>>(
        ph, W0, pWh, pWhb, a0, pf1, pf2, FEAT, 0L, (long)FEAT * DH, (long)N_NODES * DH);
    gat_atten_bf<<<dim3(N_NODES, HEADS), 128>>>(
        pWhb, pf1, pf2, pcols, pdeg, pact0, (long)N_NODES * DH, (long)DH);

    // layer 1
    sgemm_fused<128, 128, 16, 8, 8, true><<<dim3(N_NODES / 128, 1, HEADS), 256>>>(
        pact0, W1, pWh, pWhb, a1, pf1, pf2, DH,
        (long)N_NODES * DH, (long)DH * DH, (long)N_NODES * DH);
    gat_atten_bf<<<dim3(N_NODES, HEADS), 128>>>(
        pWhb, pf1, pf2, pcols, pdeg, phc, (long)DH, (long)HEADS * DH);

    // output layer
    sgemm_fused<128, 64, 16, 8, 4, false><<<dim3(N_NODES / 128, 1, 1), 256>>>(
        phc, Wo, pWhc, nullptr, ao, pf1, pf2, HEADS * DH, 0L, 0L, 0L);
    gat_atten_f32<<<N_NODES, 128>>>(pWhc, pf1, pf2, pcols, pdeg, out);
}

// round 13
// speedup vs baseline: 2.0834x; 1.2465x over previous
#include <cuda_runtime.h>
#include <cuda_bf16.h>
#include <math.h>

#define N_NODES 3072
#define FEAT    256
#define HEADS   8
#define DH      128
#define DOUT    64
#define MAXD    512

// ---------------- device scratch ----------------
__device__ float g_h[N_NODES * FEAT];
__device__ int   g_cols[N_NODES * MAXD];
__device__ int   g_deg[N_NODES];
__device__ __nv_bfloat162 g_Whb[HEADS * N_NODES * (DH/2)];
__device__ float g_act0[HEADS * N_NODES * DH];
__device__ float g_hc[N_NODES * HEADS * DH];
__device__ float g_Whc[N_NODES * DOUT];
__device__ float g_f1[HEADS * N_NODES];
__device__ float g_f2[HEADS * N_NODES];

// ---------------- packed f32x2 helpers (sm_103a FFMA2) ----------------
__device__ __forceinline__ unsigned long long pk2(unsigned lo, unsigned hi) {
    unsigned long long r;
    asm("mov.b64 %0,{%1,%2};" : "=l"(r) : "r"(lo), "r"(hi));
    return r;
}
__device__ __forceinline__ unsigned long long pkdup(float x) {
    unsigned u = __float_as_uint(x);
    unsigned long long r;
    asm("mov.b64 %0,{%1,%1};" : "=l"(r) : "r"(u));
    return r;
}
__device__ __forceinline__ void upk2(unsigned long long v, float& a, float& b) {
    unsigned lo, hi;
    asm("mov.b64 {%0,%1},%2;" : "=r"(lo), "=r"(hi) : "l"(v));
    a = __int_as_float(lo); b = __int_as_float(hi);
}
__device__ __forceinline__ unsigned long long ffma2(unsigned long long a,
                                                    unsigned long long b,
                                                    unsigned long long c) {
    unsigned long long d;
    asm("fma.rn.f32x2 %0,%1,%2,%3;" : "=l"(d) : "l"(a), "l"(b), "l"(c));
    return d;
}

// ---------------- mergeState ----------------
__global__ void merge_state(const float* __restrict__ x, const int* __restrict__ obs,
                            const float* __restrict__ theta, float* __restrict__ h)
{
    int idx = blockIdx.x * blockDim.x + threadIdx.x;
    const int total = N_NODES * FEAT / 4;
    if (idx >= total) return;
    int row = idx / (FEAT / 4);
    float4 v = reinterpret_cast<const float4*>(x)[idx];
    if (obs[row] == 1) {
        float4 t = reinterpret_cast<const float4*>(theta)[idx % (FEAT / 4)];
        v.x += t.x; v.y += t.y; v.z += t.z; v.w += t.w;
    }
    reinterpret_cast<float4*>(h)[idx] = v;
}

// ---------------- build ELL adjacency ----------------
__global__ void build_ell(const float* __restrict__ adj, int* __restrict__ cols,
                          int* __restrict__ degs)
{
    int i = blockIdx.x;
    __shared__ int cnt;
    if (threadIdx.x == 0) cnt = 0;
    __syncthreads();
    const float* row = adj + (size_t)i * N_NODES;
    for (int j = threadIdx.x; j < N_NODES; j += blockDim.x) {
        if (row[j] > 0.f) {
            int p = atomicAdd(&cnt, 1);
            if (p < MAXD) cols[i * MAXD + p] = j;
        }
    }
    __syncthreads();
    if (threadIdx.x == 0) degs[i] = cnt < MAXD ? cnt : MAXD;
}

// ---------------- tiled batched GEMM (FFMA2 mainloop) + fused f1/f2 epilogue ----------------
// BN == full output width; fp32 C written only when !BF16OUT, bf16 copy when BF16OUT.
template <int BM, int BN, int BK, int TM, int TN, bool BF16OUT>
__global__ __launch_bounds__(256)
void sgemm_fused(const float* __restrict__ A, const float* __restrict__ B,
                 float* __restrict__ C, __nv_bfloat162* __restrict__ Cb,
                 const float* __restrict__ avec,
                 float* __restrict__ f1, float* __restrict__ f2,
                 int K, long sA, long sB, long sC)
{
    constexpr int TX = BN / TN;
    constexpr int TY = BM / TM;
    constexpr int NT = TX * TY;
    static_assert(TX == 16, "epilogue reduction assumes TX=16");
    static_assert(TN % 2 == 0 && TM % 2 == 0, "FFMA2 packing");
    __shared__ float As[BK][BM];
    __shared__ float Bs[BK][BN];
    __shared__ float a1s[BN], a2s[BN];

    int z = blockIdx.z;
    A += (long)z * sA;  B += (long)z * sB;
    int bm = blockIdx.x;
    int tid = threadIdx.x;
    int tx = tid % TX, ty = tid / TX;

    if (tid < BN)          a1s[tid] = avec[z * 2 * BN + tid];
    else if (tid < 2 * BN) a2s[tid - BN] = avec[z * 2 * BN + tid];

    unsigned long long accp[TM][TN / 2];
    #pragma unroll
    for (int m = 0; m < TM; m++)
        #pragma unroll
        for (int n = 0; n < TN / 2; n++) accp[m][n] = 0ULL;

    constexpr int A_UNITS = BM * BK / 4;
    constexpr int B_UNITS = BK * BN / 4;

    for (int k0 = 0; k0 < K; k0 += BK) {
        for (int u = tid; u < A_UNITS; u += NT) {
            int r  = u / (BK / 4);
            int c4 = (u % (BK / 4)) * 4;
            float4 v = *reinterpret_cast<const float4*>(
                A + (long)(bm * BM + r) * K + k0 + c4);
            As[c4 + 0][r] = v.x; As[c4 + 1][r] = v.y;
            As[c4 + 2][r] = v.z; As[c4 + 3][r] = v.w;
        }
        for (int u = tid; u < B_UNITS; u += NT) {
            int r  = u / (BN / 4);
            int c4 = (u % (BN / 4)) * 4;
            *reinterpret_cast<float4*>(&Bs[r][c4]) =
                *reinterpret_cast<const float4*>(B + (long)(k0 + r) * BN + c4);
        }
        __syncthreads();
        #pragma unroll
        for (int kk = 0; kk < BK; kk++) {
            // A: TM/2 LDS.64, broadcast-packed per scalar
            unsigned long long rap[TM];
            #pragma unroll
            for (int j = 0; j < TM / 2; j++) {
                float2 a2 = *reinterpret_cast<const float2*>(&As[kk][ty * TM + 2 * j]);
                rap[2 * j]     = pkdup(a2.x);
                rap[2 * j + 1] = pkdup(a2.y);
            }
            // B: TN/2 LDS.64 packed pairs
            unsigned long long rbp[TN / 2];
            #pragma unroll
            for (int n = 0; n < TN / 2; n++)
                rbp[n] = *reinterpret_cast<const unsigned long long*>(
                    &Bs[kk][tx * TN + 2 * n]);
            #pragma unroll
            for (int m = 0; m < TM; m++)
                #pragma unroll
                for (int n = 0; n < TN / 2; n++)
                    accp[m][n] = ffma2(rap[m], rbp[n], accp[m][n]);
        }
        __syncthreads();
    }

    #pragma unroll
    for (int m = 0; m < TM; m++) {
        float acc[TN];
        #pragma unroll
        for (int n = 0; n < TN / 2; n++) upk2(accp[m][n], acc[2 * n], acc[2 * n + 1]);

        int row = bm * BM + ty * TM + m;
        if (!BF16OUT) {
            float* crow = C + (long)z * sC + (long)row * BN + tx * TN;
            #pragma unroll
            for (int n = 0; n < TN; n++) crow[n] = acc[n];
        } else {
            __nv_bfloat162 pk[TN / 2];
            #pragma unroll
            for (int n = 0; n < TN; n += 2)
                pk[n / 2] = __floats2bfloat162_rn(acc[n], acc[n + 1]);
            __nv_bfloat162* brow = Cb + ((long)z * N_NODES + row) * (BN / 2) + tx * (TN / 2);
            #pragma unroll
            for (int n2 = 0; n2 < TN / 2; n2++) brow[n2] = pk[n2];
        }

        float s1 = 0.f, s2 = 0.f;
        #pragma unroll
        for (int n = 0; n < TN; n++) {
            int c = tx * TN + n;
            s1 += acc[n] * a1s[c];
            s2 += acc[n] * a2s[c];
        }
        #pragma unroll
        for (int o = 8; o; o >>= 1) {
            s1 += __shfl_xor_sync(0xffffffffu, s1, o, 16);
            s2 += __shfl_xor_sync(0xffffffffu, s2, o, 16);
        }
        if (tx == 0) {
            f1[z * N_NODES + row] = s1;
            f2[z * N_NODES + row] = s2;
        }
    }
}

// ---------------- sparse softmax (no max-shift) + bf16 gather (DH=128) ----------------
__global__ __launch_bounds__(128)
void gat_atten_bf(const __nv_bfloat162* __restrict__ Whb,
                  const float* __restrict__ f1v, const float* __restrict__ f2v,
                  const int* __restrict__ cols, const int* __restrict__ degs,
                  float* __restrict__ out,
                  long outHeadStride, long outRowStride)
{
    __shared__ int   s_off[MAXD];
    __shared__ float s_w[MAXD];
    __shared__ float red[4];
    __shared__ float part[4][DH];

    int i = blockIdx.x, h = blockIdx.y, t = threadIdx.x;
    int wid = t >> 5, lane = t & 31;
    int deg = degs[i];
    const int* crow = cols + (size_t)i * MAXD;
    const float fi = f1v[h * N_NODES + i];
    const float* f2h = f2v + h * N_NODES;

    // single pass: e = leaky(f1+f2), w = exp(e) (no max-shift; |e| << 88), sum
    float lsum = 0.f;
    for (int k = t; k < deg; k += 128) {
        int c = crow[k];
        s_off[k] = c << 8;
        float e = fi + f2h[c];
        e = e > 0.f ? e : 0.2f * e;
        float w = __expf(e);
        s_w[k] = w;
        lsum += w;
    }
    #pragma unroll
    for (int o = 16; o; o >>= 1) lsum += __shfl_xor_sync(0xffffffffu, lsum, o);
    if (lane == 0) red[wid] = lsum;
    __syncthreads();
    float inv = 1.0f / (red[0] + red[1] + red[2] + red[3]);

    // warp-per-edge gather with FFMA2
    const char* base = (const char*)(Whb + (long)h * N_NODES * (DH / 2)) + lane * 8;
    unsigned long long acc0 = 0ULL, acc1 = 0ULL;
    #pragma unroll 2
    for (int k = wid; k < deg; k += 4) {
        uint2 u = *(const uint2*)(base + s_off[k]);
        unsigned wb = __float_as_uint(s_w[k]);
        unsigned long long wp = pk2(wb, wb);
        acc0 = ffma2(pk2(u.x << 16, u.x & 0xffff0000u), wp, acc0);
        acc1 = ffma2(pk2(u.y << 16, u.y & 0xffff0000u), wp, acc1);
    }
    float f0, f1x, f2x, f3;
    upk2(acc0, f0, f1x);
    upk2(acc1, f2x, f3);
    part[wid][4 * lane + 0] = f0;
    part[wid][4 * lane + 1] = f1x;
    part[wid][4 * lane + 2] = f2x;
    part[wid][4 * lane + 3] = f3;
    __syncthreads();

    float v = (part[0][t] + part[1][t] + part[2][t] + part[3][t]) * inv;
    v = v > 0.f ? v : expm1f(v);
    out[(long)h * outHeadStride + (long)i * outRowStride + t] = v;
}

// ---------------- fp32 gather for output layer (D=64) ----------------
__global__ __launch_bounds__(128)
void gat_atten_f32(const float* __restrict__ Wh,
                   const float* __restrict__ f1v, const float* __restrict__ f2v,
                   const int* __restrict__ cols, const int* __restrict__ degs,
                   float* __restrict__ out)
{
    __shared__ int   s_off[MAXD];
    __shared__ float s_w[MAXD];
    __shared__ float red[4];
    __shared__ float part[4][DOUT];

    int i = blockIdx.x, t = threadIdx.x;
    int wid = t >> 5, lane = t & 31;
    int deg = degs[i];
    const int* crow = cols + (size_t)i * MAXD;
    const float fi = f1v[i];

    float lsum = 0.f;
    for (int k = t; k < deg; k += 128) {
        int c = crow[k];
        s_off[k] = c << 8;
        float e = fi + f2v[c];
        e = e > 0.f ? e : 0.2f * e;
        float w = __expf(e);
        s_w[k] = w;
        lsum += w;
    }
    #pragma unroll
    for (int o = 16; o; o >>= 1) lsum += __shfl_xor_sync(0xffffffffu, lsum, o);
    if (lane == 0) red[wid] = lsum;
    __syncthreads();
    float inv = 1.0f / (red[0] + red[1] + red[2] + red[3]);

    const char* base = (const char*)Wh + lane * 8;
    unsigned long long acc = 0ULL;
    #pragma unroll 2
    for (int k = wid; k < deg; k += 4) {
        unsigned long long u = *(const unsigned long long*)(base + s_off[k]);
        unsigned wb = __float_as_uint(s_w[k]);
        acc = ffma2(u, pk2(wb, wb), acc);
    }
    float f0, f1x;
    upk2(acc, f0, f1x);
    part[wid][2 * lane + 0] = f0;
    part[wid][2 * lane + 1] = f1x;
    __syncthreads();

    if (t < DOUT) {
        float v = (part[0][t] + part[1][t] + part[2][t] + part[3][t]) * inv;
        v = v > 0.f ? v : expm1f(v);
        out[(long)i * DOUT + t] = v;
    }
}

// ---------------- launch ----------------
extern "C" void kernel_launch(void* const* d_in, const int* in_sizes, int n_in,
                              void* d_out, int out_size)
{
    const float* x     = (const float*)d_in[0];
    const float* adj   = (const float*)d_in[1];
    const int*   obs   = (const int*)  d_in[2];
    const float* theta = (const float*)d_in[4];
    const float* W0    = (const float*)d_in[5];
    const float* a0    = (const float*)d_in[6];
    const float* W1    = (const float*)d_in[7];
    const float* a1    = (const float*)d_in[8];
    const float* Wo    = (const float*)d_in[9];
    const float* ao    = (const float*)d_in[10];
    float* out = (float*)d_out;

    float *ph, *pact0, *phc, *pWhc, *pf1, *pf2;
    __nv_bfloat162* pWhb;
    int *pcols, *pdeg;
    cudaGetSymbolAddress((void**)&ph,    g_h);
    cudaGetSymbolAddress((void**)&pcols, g_cols);
    cudaGetSymbolAddress((void**)&pdeg,  g_deg);
    cudaGetSymbolAddress((void**)&pWhb,  g_Whb);
    cudaGetSymbolAddress((void**)&pact0, g_act0);
    cudaGetSymbolAddress((void**)&phc,   g_hc);
    cudaGetSymbolAddress((void**)&pWhc,  g_Whc);
    cudaGetSymbolAddress((void**)&pf1,   g_f1);
    cudaGetSymbolAddress((void**)&pf2,   g_f2);

    merge_state<<<(N_NODES * FEAT / 4 + 255) / 256, 256>>>(x, obs, theta, ph);
    build_ell<<<N_NODES, 256>>>(adj, pcols, pdeg);

    // layer 0
    sgemm_fused<128, 128, 16, 8, 8, true><<<dim3(N_NODES / 128, 1, HEADS), 256>>>(
        ph, W0, nullptr, pWhb, a0, pf1, pf2, FEAT, 0L, (long)FEAT * DH, 0L);
    gat_atten_bf<<<dim3(N_NODES, HEADS), 128>>>(
        pWhb, pf1, pf2, pcols, pdeg, pact0, (long)N_NODES * DH, (long)DH);

    // layer 1
    sgemm_fused<128, 128, 16, 8, 8, true><<<dim3(N_NODES / 128, 1, HEADS), 256>>>(
        pact0, W1, nullptr, pWhb, a1, pf1, pf2, DH,
        (long)N_NODES * DH, (long)DH * DH, 0L);
    gat_atten_bf<<<dim3(N_NODES, HEADS), 128>>>(
        pWhb, pf1, pf2, pcols, pdeg, phc, (long)DH, (long)HEADS * DH);

    // output layer
    sgemm_fused<128, 64, 16, 8, 4, false><<<dim3(N_NODES / 128, 1, 1), 256>>>(
        phc, Wo, pWhc, nullptr, ao, pf1, pf2, HEADS * DH, 0L, 0L, 0L);
    gat_atten_f32<<<N_NODES, 128>>>(pWhc, pf1, pf2, pcols, pdeg, out);
}

// round 14
// speedup vs baseline: 2.1985x; 1.0553x over previous
#include <cuda_runtime.h>
#include <cuda_bf16.h>
#include <math.h>

#define N_NODES 3072
#define FEAT    256
#define HEADS   8
#define DH      128
#define DOUT    64
#define MAXD    512

// ---------------- device scratch ----------------
__device__ __align__(256) float g_h[N_NODES * FEAT];
__device__ int   g_cols[N_NODES * MAXD];
__device__ int   g_deg[N_NODES];
__device__ __align__(256) __nv_bfloat162 g_Whb[HEADS * N_NODES * (DH/2)];
__device__ __align__(256) float g_act0[HEADS * N_NODES * DH];
__device__ __align__(256) float g_hc[N_NODES * HEADS * DH];
__device__ __align__(256) float g_Whc[N_NODES * DOUT];
__device__ float g_f1[HEADS * N_NODES];
__device__ float g_f2[HEADS * N_NODES];

// ---------------- packed f32x2 helpers (sm_103a FFMA2) ----------------
__device__ __forceinline__ unsigned long long pk2(unsigned lo, unsigned hi) {
    unsigned long long r;
    asm("mov.b64 %0,{%1,%2};" : "=l"(r) : "r"(lo), "r"(hi));
    return r;
}
__device__ __forceinline__ unsigned long long pkdup(float x) {
    unsigned u = __float_as_uint(x);
    unsigned long long r;
    asm("mov.b64 %0,{%1,%1};" : "=l"(r) : "r"(u));
    return r;
}
__device__ __forceinline__ void upk2(unsigned long long v, float& a, float& b) {
    unsigned lo, hi;
    asm("mov.b64 {%0,%1},%2;" : "=r"(lo), "=r"(hi) : "l"(v));
    a = __int_as_float(lo); b = __int_as_float(hi);
}
__device__ __forceinline__ unsigned long long ffma2(unsigned long long a,
                                                    unsigned long long b,
                                                    unsigned long long c) {
    unsigned long long d;
    asm("fma.rn.f32x2 %0,%1,%2,%3;" : "=l"(d) : "l"(a), "l"(b), "l"(c));
    return d;
}

// ---------------- mergeState ----------------
__global__ void merge_state(const float* __restrict__ x, const int* __restrict__ obs,
                            const float* __restrict__ theta, float* __restrict__ h)
{
    int idx = blockIdx.x * blockDim.x + threadIdx.x;
    const int total = N_NODES * FEAT / 4;
    if (idx >= total) return;
    int row = idx / (FEAT / 4);
    float4 v = reinterpret_cast<const float4*>(x)[idx];
    if (obs[row] == 1) {
        float4 t = reinterpret_cast<const float4*>(theta)[idx % (FEAT / 4)];
        v.x += t.x; v.y += t.y; v.z += t.z; v.w += t.w;
    }
    reinterpret_cast<float4*>(h)[idx] = v;
}

// ---------------- build ELL adjacency (vectorized float4 scan) ----------------
__global__ void build_ell(const float* __restrict__ adj, int* __restrict__ cols,
                          int* __restrict__ degs)
{
    int i = blockIdx.x;
    __shared__ int cnt;
    if (threadIdx.x == 0) cnt = 0;
    __syncthreads();
    const float4* row4 = reinterpret_cast<const float4*>(adj + (size_t)i * N_NODES);
    int* crow = cols + i * MAXD;
    for (int j = threadIdx.x; j < N_NODES / 4; j += blockDim.x) {
        float4 v = row4[j];
        int j4 = j * 4;
        if (v.x > 0.f) { int p = atomicAdd(&cnt, 1); if (p < MAXD) crow[p] = j4; }
        if (v.y > 0.f) { int p = atomicAdd(&cnt, 1); if (p < MAXD) crow[p] = j4 + 1; }
        if (v.z > 0.f) { int p = atomicAdd(&cnt, 1); if (p < MAXD) crow[p] = j4 + 2; }
        if (v.w > 0.f) { int p = atomicAdd(&cnt, 1); if (p < MAXD) crow[p] = j4 + 3; }
    }
    __syncthreads();
    if (threadIdx.x == 0) degs[i] = cnt < MAXD ? cnt : MAXD;
}

// ---------------- tiled batched GEMM (FFMA2 mainloop) + fused f1/f2 epilogue ----------------
template <int BM, int BN, int BK, int TM, int TN, bool BF16OUT>
__global__ __launch_bounds__(256)
void sgemm_fused(const float* __restrict__ A, const float* __restrict__ B,
                 float* __restrict__ C, __nv_bfloat162* __restrict__ Cb,
                 const float* __restrict__ avec,
                 float* __restrict__ f1, float* __restrict__ f2,
                 int K, long sA, long sB, long sC)
{
    constexpr int TX = BN / TN;
    constexpr int TY = BM / TM;
    constexpr int NT = TX * TY;
    static_assert(TX == 16, "epilogue reduction assumes TX=16");
    static_assert(TN % 2 == 0 && TM % 2 == 0, "FFMA2 packing");
    __shared__ float As[BK][BM];
    __shared__ float Bs[BK][BN];
    __shared__ float a1s[BN], a2s[BN];

    int z = blockIdx.z;
    A += (long)z * sA;  B += (long)z * sB;
    int bm = blockIdx.x;
    int tid = threadIdx.x;
    int tx = tid % TX, ty = tid / TX;

    if (tid < BN)          a1s[tid] = avec[z * 2 * BN + tid];
    else if (tid < 2 * BN) a2s[tid - BN] = avec[z * 2 * BN + tid];

    unsigned long long accp[TM][TN / 2];
    #pragma unroll
    for (int m = 0; m < TM; m++)
        #pragma unroll
        for (int n = 0; n < TN / 2; n++) accp[m][n] = 0ULL;

    constexpr int A_UNITS = BM * BK / 4;
    constexpr int B_UNITS = BK * BN / 4;

    for (int k0 = 0; k0 < K; k0 += BK) {
        for (int u = tid; u < A_UNITS; u += NT) {
            int r  = u / (BK / 4);
            int c4 = (u % (BK / 4)) * 4;
            float4 v = *reinterpret_cast<const float4*>(
                A + (long)(bm * BM + r) * K + k0 + c4);
            As[c4 + 0][r] = v.x; As[c4 + 1][r] = v.y;
            As[c4 + 2][r] = v.z; As[c4 + 3][r] = v.w;
        }
        for (int u = tid; u < B_UNITS; u += NT) {
            int r  = u / (BN / 4);
            int c4 = (u % (BN / 4)) * 4;
            *reinterpret_cast<float4*>(&Bs[r][c4]) =
                *reinterpret_cast<const float4*>(B + (long)(k0 + r) * BN + c4);
        }
        __syncthreads();
        #pragma unroll
        for (int kk = 0; kk < BK; kk++) {
            unsigned long long rap[TM];
            #pragma unroll
            for (int j = 0; j < TM / 2; j++) {
                float2 a2 = *reinterpret_cast<const float2*>(&As[kk][ty * TM + 2 * j]);
                rap[2 * j]     = pkdup(a2.x);
                rap[2 * j + 1] = pkdup(a2.y);
            }
            unsigned long long rbp[TN / 2];
            #pragma unroll
            for (int n = 0; n < TN / 2; n++)
                rbp[n] = *reinterpret_cast<const unsigned long long*>(
                    &Bs[kk][tx * TN + 2 * n]);
            #pragma unroll
            for (int m = 0; m < TM; m++)
                #pragma unroll
                for (int n = 0; n < TN / 2; n++)
                    accp[m][n] = ffma2(rap[m], rbp[n], accp[m][n]);
        }
        __syncthreads();
    }

    #pragma unroll
    for (int m = 0; m < TM; m++) {
        float acc[TN];
        #pragma unroll
        for (int n = 0; n < TN / 2; n++) upk2(accp[m][n], acc[2 * n], acc[2 * n + 1]);

        int row = bm * BM + ty * TM + m;
        if (!BF16OUT) {
            float* crow = C + (long)z * sC + (long)row * BN + tx * TN;
            #pragma unroll
            for (int n = 0; n < TN; n++) crow[n] = acc[n];
        } else {
            __nv_bfloat162 pk[TN / 2];
            #pragma unroll
            for (int n = 0; n < TN; n += 2)
                pk[n / 2] = __floats2bfloat162_rn(acc[n], acc[n + 1]);
            __nv_bfloat162* brow = Cb + ((long)z * N_NODES + row) * (BN / 2) + tx * (TN / 2);
            #pragma unroll
            for (int n2 = 0; n2 < TN / 2; n2++) brow[n2] = pk[n2];
        }

        float s1 = 0.f, s2 = 0.f;
        #pragma unroll
        for (int n = 0; n < TN; n++) {
            int c = tx * TN + n;
            s1 += acc[n] * a1s[c];
            s2 += acc[n] * a2s[c];
        }
        #pragma unroll
        for (int o = 8; o; o >>= 1) {
            s1 += __shfl_xor_sync(0xffffffffu, s1, o, 16);
            s2 += __shfl_xor_sync(0xffffffffu, s2, o, 16);
        }
        if (tx == 0) {
            f1[z * N_NODES + row] = s1;
            f2[z * N_NODES + row] = s2;
        }
    }
}

// ---------------- sparse softmax + bf16 gather (DH=128) ----------------
// 128 threads = 4 warps; each warp processes 2 edges/iter via 16-lane halves
// (uint4 = 16B per lane covers a full 256B row per half).
__global__ __launch_bounds__(128)
void gat_atten_bf(const __nv_bfloat162* __restrict__ Whb,
                  const float* __restrict__ f1v, const float* __restrict__ f2v,
                  const int* __restrict__ cols, const int* __restrict__ degs,
                  float* __restrict__ out,
                  long outHeadStride, long outRowStride)
{
    __shared__ float2 s_wo[MAXD];     // {weight, byte-offset as float bits}
    __shared__ float red[4];
    __shared__ float part[8][DH];

    int i = blockIdx.x, h = blockIdx.y, t = threadIdx.x;
    int wid = t >> 5, lane = t & 31;
    int half = lane >> 4, hl = lane & 15;
    int deg = degs[i];
    const int* crow = cols + (size_t)i * MAXD;
    const float fi = f1v[h * N_NODES + i];
    const float* f2h = f2v + h * N_NODES;

    // single pass: w = exp(leaky(f1+f2)) (no max-shift; |e| << 88), sum
    float lsum = 0.f;
    for (int k = t; k < deg; k += 128) {
        int c = crow[k];
        float e = fi + f2h[c];
        e = e > 0.f ? e : 0.2f * e;
        float w = __expf(e);
        s_wo[k] = make_float2(w, __int_as_float(c << 8));
        lsum += w;
    }
    #pragma unroll
    for (int o = 16; o; o >>= 1) lsum += __shfl_xor_sync(0xffffffffu, lsum, o);
    if (lane == 0) red[wid] = lsum;
    __syncthreads();
    float inv = 1.0f / (red[0] + red[1] + red[2] + red[3]);

    // gather: 2 edges per warp-iteration, LDG.128 per lane
    const char* base = (const char*)(Whb + (long)h * N_NODES * (DH / 2)) + hl * 16;
    unsigned long long acc0 = 0ULL, acc1 = 0ULL, acc2 = 0ULL, acc3 = 0ULL;
    for (int k = wid * 2 + half; k < deg; k += 8) {
        float2 wo = s_wo[k];
        uint4 u = *(const uint4*)(base + __float_as_int(wo.y));
        unsigned wb = __float_as_uint(wo.x);
        unsigned long long wp = pk2(wb, wb);
        acc0 = ffma2(pk2(u.x << 16, u.x & 0xffff0000u), wp, acc0);
        acc1 = ffma2(pk2(u.y << 16, u.y & 0xffff0000u), wp, acc1);
        acc2 = ffma2(pk2(u.z << 16, u.z & 0xffff0000u), wp, acc2);
        acc3 = ffma2(pk2(u.w << 16, u.w & 0xffff0000u), wp, acc3);
    }
    float f[8];
    upk2(acc0, f[0], f[1]);
    upk2(acc1, f[2], f[3]);
    upk2(acc2, f[4], f[5]);
    upk2(acc3, f[6], f[7]);
    int slot = 2 * wid + half;
    #pragma unroll
    for (int j = 0; j < 8; j++) part[slot][8 * hl + j] = f[j];
    __syncthreads();

    float v = 0.f;
    #pragma unroll
    for (int p = 0; p < 8; p++) v += part[p][t];
    v *= inv;
    v = v > 0.f ? v : expm1f(v);
    out[(long)h * outHeadStride + (long)i * outRowStride + t] = v;
}

// ---------------- fp32 gather for output layer (D=64) ----------------
__global__ __launch_bounds__(128)
void gat_atten_f32(const float* __restrict__ Wh,
                   const float* __restrict__ f1v, const float* __restrict__ f2v,
                   const int* __restrict__ cols, const int* __restrict__ degs,
                   float* __restrict__ out)
{
    __shared__ float2 s_wo[MAXD];
    __shared__ float red[4];
    __shared__ float part[8][DOUT];

    int i = blockIdx.x, t = threadIdx.x;
    int wid = t >> 5, lane = t & 31;
    int half = lane >> 4, hl = lane & 15;
    int deg = degs[i];
    const int* crow = cols + (size_t)i * MAXD;
    const float fi = f1v[i];

    float lsum = 0.f;
    for (int k = t; k < deg; k += 128) {
        int c = crow[k];
        float e = fi + f2v[c];
        e = e > 0.f ? e : 0.2f * e;
        float w = __expf(e);
        s_wo[k] = make_float2(w, __int_as_float(c << 8));
        lsum += w;
    }
    #pragma unroll
    for (int o = 16; o; o >>= 1) lsum += __shfl_xor_sync(0xffffffffu, lsum, o);
    if (lane == 0) red[wid] = lsum;
    __syncthreads();
    float inv = 1.0f / (red[0] + red[1] + red[2] + red[3]);

    // 2 edges per warp-iteration: 16 lanes x 16B = 256B row (4 floats/lane)
    const char* base = (const char*)Wh + hl * 16;
    unsigned long long acc0 = 0ULL, acc1 = 0ULL;
    for (int k = wid * 2 + half; k < deg; k += 8) {
        float2 wo = s_wo[k];
        ulonglong2 u = *(const ulonglong2*)(base + __float_as_int(wo.y));
        unsigned wb = __float_as_uint(wo.x);
        unsigned long long wp = pk2(wb, wb);
        acc0 = ffma2(u.x, wp, acc0);
        acc1 = ffma2(u.y, wp, acc1);
    }
    float f[4];
    upk2(acc0, f[0], f[1]);
    upk2(acc1, f[2], f[3]);
    int slot = 2 * wid + half;
    #pragma unroll
    for (int j = 0; j < 4; j++) part[slot][4 * hl + j] = f[j];
    __syncthreads();

    if (t < DOUT) {
        float v = 0.f;
        #pragma unroll
        for (int p = 0; p < 8; p++) v += part[p][t];
        v *= inv;
        v = v > 0.f ? v : expm1f(v);
        out[(long)i * DOUT + t] = v;
    }
}

// ---------------- launch ----------------
extern "C" void kernel_launch(void* const* d_in, const int* in_sizes, int n_in,
                              void* d_out, int out_size)
{
    const float* x     = (const float*)d_in[0];
    const float* adj   = (const float*)d_in[1];
    const int*   obs   = (const int*)  d_in[2];
    const float* theta = (const float*)d_in[4];
    const float* W0    = (const float*)d_in[5];
    const float* a0    = (const float*)d_in[6];
    const float* W1    = (const float*)d_in[7];
    const float* a1    = (const float*)d_in[8];
    const float* Wo    = (const float*)d_in[9];
    const float* ao    = (const float*)d_in[10];
    float* out = (float*)d_out;

    float *ph, *pact0, *phc, *pWhc, *pf1, *pf2;
    __nv_bfloat162* pWhb;
    int *pcols, *pdeg;
    cudaGetSymbolAddress((void**)&ph,    g_h);
    cudaGetSymbolAddress((void**)&pcols, g_cols);
    cudaGetSymbolAddress((void**)&pdeg,  g_deg);
    cudaGetSymbolAddress((void**)&pWhb,  g_Whb);
    cudaGetSymbolAddress((void**)&pact0, g_act0);
    cudaGetSymbolAddress((void**)&phc,   g_hc);
    cudaGetSymbolAddress((void**)&pWhc,  g_Whc);
    cudaGetSymbolAddress((void**)&pf1,   g_f1);
    cudaGetSymbolAddress((void**)&pf2,   g_f2);

    merge_state<<<(N_NODES * FEAT / 4 + 255) / 256, 256>>>(x, obs, theta, ph);
    build_ell<<<N_NODES, 256>>>(adj, pcols, pdeg);

    // layer 0
    sgemm_fused<128, 128, 16, 8, 8, true><<<dim3(N_NODES / 128, 1, HEADS), 256>>>(
        ph, W0, nullptr, pWhb, a0, pf1, pf2, FEAT, 0L, (long)FEAT * DH, 0L);
    gat_atten_bf<<<dim3(N_NODES, HEADS), 128>>>(
        pWhb, pf1, pf2, pcols, pdeg, pact0, (long)N_NODES * DH, (long)DH);

    // layer 1
    sgemm_fused<128, 128, 16, 8, 8, true><<<dim3(N_NODES / 128, 1, HEADS), 256>>>(
        pact0, W1, nullptr, pWhb, a1, pf1, pf2, DH,
        (long)N_NODES * DH, (long)DH * DH, 0L);
    gat_atten_bf<<<dim3(N_NODES, HEADS), 128>>>(
        pWhb, pf1, pf2, pcols, pdeg, phc, (long)DH, (long)HEADS * DH);

    // output layer
    sgemm_fused<128, 64, 16, 8, 4, false><<<dim3(N_NODES / 128, 1, 1), 256>>>(
        phc, Wo, pWhc, nullptr, ao, pf1, pf2, HEADS * DH, 0L, 0L, 0L);
    gat_atten_f32<<<N_NODES, 128>>>(pWhc, pf1, pf2, pcols, pdeg, out);
}